// round 6
// baseline (speedup 1.0000x reference)
#include <cuda_runtime.h>
#include <cuda_bf16.h>
#include <cstddef>

#define N_NODES 50000
#define N_EDGES 800000
#define F 128

typedef unsigned long long u64;

// ---------------- scratch (no allocation allowed -> device globals) ----------
__device__ __align__(16) float g_agg[(size_t)N_NODES * F];
__device__ __align__(16) float g_h  [(size_t)N_NODES * F];
__device__ __align__(16) float g_x  [(size_t)N_NODES * F];
__device__ float g_deg[N_NODES];
__device__ float g_invdeg[N_NODES];

// ---------------- Blackwell packed fp32 helpers ------------------------------
__device__ __forceinline__ u64 pack2(float lo, float hi) {
    u64 d; asm("mov.b64 %0, {%1, %2};" : "=l"(d) : "f"(lo), "f"(hi)); return d;
}
__device__ __forceinline__ void unpack2(float& lo, float& hi, u64 a) {
    asm("mov.b64 {%0, %1}, %2;" : "=f"(lo), "=f"(hi) : "l"(a));
}
// FFMA2: two independent rn fp32 FMAs per instruction (sm_103a packed pipe)
__device__ __forceinline__ u64 fma2(u64 a, u64 b, u64 c) {
    u64 d; asm("fma.rn.f32x2 %0, %1, %2, %3;" : "=l"(d) : "l"(a), "l"(b), "l"(c));
    return d;
}

// ---------------- degree ----------------------------------------------------
__global__ void deg_kernel(const int* __restrict__ dst) {
    int e = blockIdx.x * blockDim.x + threadIdx.x;
    if (e < N_EDGES) atomicAdd(&g_deg[dst[e]], 1.0f);
}

__global__ void invdeg_kernel() {
    int n = blockIdx.x * blockDim.x + threadIdx.x;
    if (n < N_NODES) g_invdeg[n] = 1.0f / fmaxf(g_deg[n], 1.0f);
}

// ---------------- edge scatter: g_agg[dst] += X[src] -------------------------
// one warp per edge, lane handles 16B (float4), vector RED to L2.
// Feature table (25.6 MB) is L2-resident; REDG spread-addr ~0.854 cyc/lane.
__global__ void scatter_kernel(const float* __restrict__ X,
                               const int* __restrict__ src,
                               const int* __restrict__ dst) {
    int gt   = blockIdx.x * blockDim.x + threadIdx.x;
    int warp = gt >> 5;
    int lane = gt & 31;
    if (warp >= N_EDGES) return;
    int s = __ldg(&src[warp]);
    int d = __ldg(&dst[warp]);
    const float4* xs = reinterpret_cast<const float4*>(X + (size_t)s * F);
    float4 v = __ldg(&xs[lane]);
    float* outp = g_agg + (size_t)d * F + lane * 4;
    asm volatile("red.global.add.v4.f32 [%0], {%1,%2,%3,%4};"
                 :: "l"(outp), "f"(v.x), "f"(v.y), "f"(v.z), "f"(v.w)
                 : "memory");
}

// ---------------- fused GEMM: OUT = act( IN @ W^T + b ) ----------------------
// IN is either X (plain) or X + g_agg * invdeg (GIN mode), tile of 64 nodes.
// W stored k-major in smem: sWt[k][o] (even pad) -> aligned LDS.64 of adjacent
// output pairs. Input tile sIn padded to 132 (16B-aligned rows) -> LDS.128 xin.
// Thread mapping:
//   r = tid%16 -> output pairs o = {2r+32p, 2r+32p+1}, p < OUTF/32
//   c = tid/16 -> nodes n = c + 16*i, i < 4
// Per thread per 4 k-steps (OUTF=128): 4 LDS.128 (xin) + 16 LDS.64 (w) +
// 16 mov.b64 + 64 FFMA2 = 100 issue slots for 128 packed FMAs.
template <int OUTF, bool GIN, bool RELU>
__global__ void gemm_kernel(const float* __restrict__ X,
                            const float* __restrict__ AGG,
                            const float* __restrict__ W,
                            const float* __restrict__ B,
                            float* __restrict__ OUT) {
    constexpr int WPAD   = OUTF + 2;           // even -> 8B-aligned w rows
    constexpr int IPAD   = 132;                // 16B-aligned input rows
    constexpr int NP     = OUTF / 32;          // output pairs per thread
    constexpr int OSHIFT = (OUTF == 128) ? 7 : 6;

    extern __shared__ float sm[];
    float* sWt = sm;                 // [128 k][WPAD]
    float* sIn = sm + 128 * WPAD;    // [64 n][IPAD]

    const int tid = threadIdx.x;     // 256 threads
    const int n0  = blockIdx.x * 64;

    // ---- fill W transposed: lanes consecutive in o -> conflict-free STS.
    // Global read W4[o*32 + k4] is a strided gather, but W is <=64KB and
    // L2-hot across 782 blocks.
    const float4* W4 = reinterpret_cast<const float4*>(W);
    for (int idx = tid; idx < OUTF * 32; idx += 256) {
        int o  = idx & (OUTF - 1);
        int k4 = idx >> OSHIFT;               // 0..31
        float4 w = __ldg(&W4[o * 32 + k4]);
        sWt[(4 * k4 + 0) * WPAD + o] = w.x;
        sWt[(4 * k4 + 1) * WPAD + o] = w.y;
        sWt[(4 * k4 + 2) * WPAD + o] = w.z;
        sWt[(4 * k4 + 3) * WPAD + o] = w.w;
    }

    // ---- load input tile (fuse GIN self + mean-agg add)
    for (int idx = tid; idx < 64 * (F / 4); idx += 256) {
        int n  = idx >> 5;
        int k4 = idx & 31;
        int gn = n0 + n;
        float4 v = make_float4(0.f, 0.f, 0.f, 0.f);
        if (gn < N_NODES) {
            v = __ldg(&reinterpret_cast<const float4*>(X + (size_t)gn * F)[k4]);
            if (GIN) {
                float4 a = __ldg(&reinterpret_cast<const float4*>(AGG + (size_t)gn * F)[k4]);
                float inv = g_invdeg[gn];
                v.x = fmaf(a.x, inv, v.x);
                v.y = fmaf(a.y, inv, v.y);
                v.z = fmaf(a.z, inv, v.z);
                v.w = fmaf(a.w, inv, v.w);
            }
        }
        *reinterpret_cast<float4*>(sIn + n * IPAD + k4 * 4) = v;
    }
    __syncthreads();

    const int r = tid & 15;
    const int c = tid >> 4;

    u64 acc[4][NP];
    #pragma unroll
    for (int i = 0; i < 4; i++)
        #pragma unroll
        for (int p = 0; p < NP; p++) acc[i][p] = 0ull;

    #pragma unroll 2
    for (int k4 = 0; k4 < 32; k4++) {
        // one LDS.128 per node-row i covers k = 4*k4 .. 4*k4+3
        float4 xv[4];
        #pragma unroll
        for (int i = 0; i < 4; i++)
            xv[i] = *reinterpret_cast<const float4*>(sIn + (c + 16 * i) * IPAD + 4 * k4);

        #pragma unroll
        for (int kk = 0; kk < 4; kk++) {
            u64 x2[4];
            #pragma unroll
            for (int i = 0; i < 4; i++) {
                float v = (kk == 0) ? xv[i].x : (kk == 1) ? xv[i].y
                        : (kk == 2) ? xv[i].z : xv[i].w;
                x2[i] = pack2(v, v);
            }
            const float* wrow = sWt + (4 * k4 + kk) * WPAD + 2 * r;
            #pragma unroll
            for (int p = 0; p < NP; p++) {
                u64 w2 = *reinterpret_cast<const u64*>(wrow + 32 * p);  // LDS.64
                #pragma unroll
                for (int i = 0; i < 4; i++) acc[i][p] = fma2(x2[i], w2, acc[i][p]);
            }
        }
    }

    // ---- epilogue: bias (+relu), paired float2 stores (8B aligned)
    float bias0[NP], bias1[NP];
    #pragma unroll
    for (int p = 0; p < NP; p++) {
        bias0[p] = __ldg(&B[2 * r + 32 * p]);
        bias1[p] = __ldg(&B[2 * r + 32 * p + 1]);
    }

    #pragma unroll
    for (int i = 0; i < 4; i++) {
        int gn = n0 + c + 16 * i;
        if (gn >= N_NODES) continue;
        float* orow = OUT + (size_t)gn * OUTF;
        #pragma unroll
        for (int p = 0; p < NP; p++) {
            float v0, v1;
            unpack2(v0, v1, acc[i][p]);
            v0 += bias0[p];
            v1 += bias1[p];
            if (RELU) { v0 = fmaxf(v0, 0.f); v1 = fmaxf(v1, 0.f); }
            *reinterpret_cast<float2*>(orow + 2 * r + 32 * p) = make_float2(v0, v1);
        }
    }
}

// ---------------- launch -----------------------------------------------------
extern "C" void kernel_launch(void* const* d_in, const int* in_sizes, int n_in,
                              void* d_out, int out_size) {
    const float* features = (const float*)d_in[0];
    const int*   src      = (const int*)d_in[1];
    const int*   dst      = (const int*)d_in[2];
    const float* W1a = (const float*)d_in[3];  const float* b1a = (const float*)d_in[4];
    const float* W1b = (const float*)d_in[5];  const float* b1b = (const float*)d_in[6];
    const float* W2a = (const float*)d_in[7];  const float* b2a = (const float*)d_in[8];
    const float* W2b = (const float*)d_in[9];  const float* b2b = (const float*)d_in[10];
    const float* W3a = (const float*)d_in[11]; const float* b3a = (const float*)d_in[12];
    const float* W3b = (const float*)d_in[13]; const float* b3b = (const float*)d_in[14];
    float* out = (float*)d_out;

    float *agg, *h, *x, *deg;
    cudaGetSymbolAddress((void**)&agg, g_agg);
    cudaGetSymbolAddress((void**)&h,   g_h);
    cudaGetSymbolAddress((void**)&x,   g_x);
    cudaGetSymbolAddress((void**)&deg, g_deg);

    const int SMEM128 = (128 * 130 + 64 * 132) * 4;  // 100352 B
    const int SMEM64  = (128 * 66  + 64 * 132) * 4;  // 67584 B
    cudaFuncSetAttribute(gemm_kernel<128, true,  true>,
                         cudaFuncAttributeMaxDynamicSharedMemorySize, SMEM128);
    cudaFuncSetAttribute(gemm_kernel<128, false, true>,
                         cudaFuncAttributeMaxDynamicSharedMemorySize, SMEM128);
    cudaFuncSetAttribute(gemm_kernel<64,  false, false>,
                         cudaFuncAttributeMaxDynamicSharedMemorySize, SMEM64);

    const int GB = (N_NODES + 63) / 64;          // 782 node-tile blocks
    const int SCAT_BLOCKS = (N_EDGES * 32 + 255) / 256;

    // degree (shared by both GIN layers)
    cudaMemsetAsync(deg, 0, N_NODES * sizeof(float));
    deg_kernel<<<(N_EDGES + 255) / 256, 256>>>(dst);
    invdeg_kernel<<<(N_NODES + 255) / 256, 256>>>();

    // ---- layer 1 ----
    cudaMemsetAsync(agg, 0, (size_t)N_NODES * F * sizeof(float));
    scatter_kernel<<<SCAT_BLOCKS, 256>>>(features, src, dst);
    gemm_kernel<128, true,  true><<<GB, 256, SMEM128>>>(features, agg, W1a, b1a, h);
    gemm_kernel<128, false, true><<<GB, 256, SMEM128>>>(h, nullptr, W1b, b1b, x);   // x1 = relu(gin1)

    // ---- layer 2 ----
    cudaMemsetAsync(agg, 0, (size_t)N_NODES * F * sizeof(float));
    scatter_kernel<<<SCAT_BLOCKS, 256>>>(x, src, dst);
    gemm_kernel<128, true,  true><<<GB, 256, SMEM128>>>(x, agg, W2a, b2a, h);
    gemm_kernel<128, false, true><<<GB, 256, SMEM128>>>(h, nullptr, W2b, b2b, agg); // x2 = relu(gin2) (reuse agg)

    // ---- head ----
    gemm_kernel<128, false, true><<<GB, 256, SMEM128>>>(agg, nullptr, W3a, b3a, h); // relu(x2 @ W3a^T + b3a)
    gemm_kernel<64,  false, false><<<GB, 256, SMEM64>>>(h, nullptr, W3b, b3b, out); // final linear, no relu
}